// round 10
// baseline (speedup 1.0000x reference)
#include <cuda_runtime.h>
#include <cuda_bf16.h>

#define Bdim 64
#define Hdim 64
#define Wdim 64
#define NPIX (Bdim * Hdim * Wdim)
#define TSTEPS 60

typedef unsigned int u32;

__device__ float g_bufs[2][NPIX * 16];

// Weight fragment images, uint4 = {B0hi, B1hi, B0lo, B1lo} (one MMA B-frag pair).
__device__ __align__(16) uint4 cW4_g[9][128][4];      // [tap][n][qt]
__device__ __align__(16) uint4 w14_g[2][8][128][4];   // [half][kt][nl][qt]
__device__ __align__(16) uint4 w24_g[16][16][4];      // [n][kt2][qt]

__device__ __forceinline__ void splitpk(float x0, float x1, u32& hi, u32& lo) {
    u32 h;
    asm("cvt.rn.bf16x2.f32 %0, %1, %2;" : "=r"(h) : "f"(x1), "f"(x0));
    float r0 = x0 - __uint_as_float(h << 16);
    float r1 = x1 - __uint_as_float(h & 0xFFFF0000u);
    u32 l;
    asm("cvt.rn.bf16x2.f32 %0, %1, %2;" : "=r"(l) : "f"(r1), "f"(r0));
    hi = h; lo = l;
}

__device__ __forceinline__ void mma_bf(float* c, u32 a0, u32 a1, u32 a2, u32 a3,
                                       u32 b0, u32 b1) {
    asm volatile(
        "mma.sync.aligned.m16n8k16.row.col.f32.bf16.bf16.f32 "
        "{%0,%1,%2,%3}, {%4,%5,%6,%7}, {%8,%9}, {%0,%1,%2,%3};"
        : "+f"(c[0]), "+f"(c[1]), "+f"(c[2]), "+f"(c[3])
        : "r"(a0), "r"(a1), "r"(a2), "r"(a3), "r"(b0), "r"(b1));
}

// ---------------- prep: build fragment images (once) ----------------
__global__ void nca_prep(const float* __restrict__ cw, const float* __restrict__ w1,
                         const float* __restrict__ w2) {
    int idx = blockIdx.x * blockDim.x + threadIdx.x;
    if (idx < 4608) {                         // conv: 9 tap x 128 n x 4 qt
        int tap = idx >> 9, rem = idx & 511;
        int n = rem >> 2, qt = rem & 3;
        int k0 = 16 * tap + 2 * qt;
        float v0 = cw[k0 * 128 + n],       v1 = cw[(k0 + 1) * 128 + n];
        float v2 = cw[(k0 + 8) * 128 + n], v3 = cw[(k0 + 9) * 128 + n];
        u32 b0h, b0l, b1h, b1l;
        splitpk(v0, v1, b0h, b0l); splitpk(v2, v3, b1h, b1l);
        cW4_g[tap][n][qt] = make_uint4(b0h, b1h, b0l, b1l);
    } else if (idx < 4608 + 8192) {           // w1: 2 hf x 8 kt x 128 nl x 4 qt
        int i = idx - 4608;
        int hf = i >> 12, rem = i & 4095;
        int kt = rem >> 9, r2 = rem & 511, nl = r2 >> 2, qt = r2 & 3;
        int n = 128 * hf + nl, k0 = 16 * kt + 2 * qt;
        float v0 = w1[k0 * 256 + n],       v1 = w1[(k0 + 1) * 256 + n];
        float v2 = w1[(k0 + 8) * 256 + n], v3 = w1[(k0 + 9) * 256 + n];
        u32 b0h, b0l, b1h, b1l;
        splitpk(v0, v1, b0h, b0l); splitpk(v2, v3, b1h, b1l);
        w14_g[hf][kt][nl][qt] = make_uint4(b0h, b1h, b0l, b1l);
    } else if (idx < 4608 + 8192 + 1024) {    // w2: 16 n x 16 kt2 x 4 qt
        int i = idx - 12800;
        int n = i >> 6, r2 = i & 63, kt = r2 >> 2, qt = r2 & 3;
        int k0 = 16 * kt + 2 * qt;
        float v0 = w2[k0 * 16 + n],       v1 = w2[(k0 + 1) * 16 + n];
        float v2 = w2[(k0 + 8) * 16 + n], v3 = w2[(k0 + 9) * 16 + n];
        u32 b0h, b0l, b1h, b1l;
        splitpk(v0, v1, b0h, b0l); splitpk(v2, v3, b1h, b1l);
        w24_g[n][kt][qt] = make_uint4(b0h, b1h, b0l, b1l);
    }
}

__global__ void nca_init(const float* __restrict__ input) {
    int pix = blockIdx.x * blockDim.x + threadIdx.x;
    if (pix < NPIX) {
        float* g = g_bufs[0] + (size_t)pix * 16;
        g[0] = input[pix];
        #pragma unroll
        for (int c = 1; c < 16; c++) g[c] = 0.0f;
    }
}

// ---------------- smem layout ----------------
#define R_HALOS 0
#define R_PART  0
#define OFF_HS  16384
#define SMEM_BYTES (16384 + 34816)   // 51200

// CTA = 1 image row (64 px), 8 warps: wm = warp&1 (m half), wn = warp>>1 (n 4-way).
__global__ __launch_bounds__(256, 3) void nca_step_h(
    int sb, const float* __restrict__ cb, const float* __restrict__ b1,
    const float* __restrict__ b2)
{
    extern __shared__ unsigned char smb[];
    uint2* haloS = (uint2*)(smb + R_HALOS);
    u32*   hS    = (u32*)(smb + OFF_HS);
    float* part  = (float*)(smb + R_PART);

    const float* __restrict__ gsrc = g_bufs[sb];
    float* __restrict__ gdst = g_bufs[sb ^ 1];

    const int tid  = threadIdx.x;
    const int lane = tid & 31;
    const int warp = tid >> 5;
    const int wm = warp & 1, wn = warp >> 1;
    const int qt = lane & 3, rt = lane >> 2;
    const int bI = blockIdx.x >> 6;
    const int h0 = blockIdx.x & 63;

    // ---- cooperative halo pre-split: 3 rows x 66 cells x 8 q8 ----
    #pragma unroll
    for (int idx = tid; idx < 1584; idx += 256) {
        int cell = idx >> 3, q8 = idx & 7;
        int rr = cell / 66, wc = cell - rr * 66;
        int hh = h0 + rr - 1, ww = wc - 1;
        float2 v = make_float2(0.f, 0.f);
        if (hh >= 0 && hh < Hdim && ww >= 0 && ww < Wdim)
            v = *(const float2*)(gsrc + ((size_t)((bI * Hdim + hh) * Wdim + ww) << 4) + 2 * q8);
        u32 hi, lo; splitpk(v.x, v.y, hi, lo);
        haloS[idx] = make_uint2(hi, lo);
    }
    __syncthreads();

    // hoisted per-warp fragment pointers
    const uint4* cwB = &cW4_g[0][32 * wn + rt][qt];               // +tap*512 +nt*32
    const uint4* w1B = &w14_g[0][0][32 * wn + rt][qt];            // +hf*4096 +kt*512 +nt*32
    const uint4* w2B = (const uint4*)w24_g + rt * 64 + wn * 8 + qt; // +nt2*512 +hf*32 +ktl*4
    const u32*   hA  = hS + (32 * wm + rt) * 136 + qt * 2;        // +mt*2176 +kt*16

    // ================= conv: M64 x N128 x K144 =================
    float acc[2][4][4];
    #pragma unroll
    for (int nt = 0; nt < 4; nt++) {
        int n0 = 32 * wn + 8 * nt + 2 * qt;
        float bb0 = __ldg(cb + n0), bb1 = __ldg(cb + n0 + 1);
        #pragma unroll
        for (int mt = 0; mt < 2; mt++) {
            acc[mt][nt][0] = bb0; acc[mt][nt][1] = bb1;
            acc[mt][nt][2] = bb0; acc[mt][nt][3] = bb1;
        }
    }
    #pragma unroll
    for (int tap = 0; tap < 9; tap++) {
        const int ky = tap / 3, kx = tap - 3 * ky;
        u32 ah[2][4], al[2][4];
        #pragma unroll
        for (int mt = 0; mt < 2; mt++) {
            int p  = 32 * wm + 16 * mt + rt;
            int c0 = ky * 66 + p + kx;
            int c1 = c0 + 8;
            uint2 A0 = haloS[c0 * 8 + qt];
            uint2 A1 = haloS[c1 * 8 + qt];
            uint2 A2 = haloS[c0 * 8 + qt + 4];
            uint2 A3 = haloS[c1 * 8 + qt + 4];
            ah[mt][0] = A0.x; al[mt][0] = A0.y;
            ah[mt][1] = A1.x; al[mt][1] = A1.y;
            ah[mt][2] = A2.x; al[mt][2] = A2.y;
            ah[mt][3] = A3.x; al[mt][3] = A3.y;
        }
        #pragma unroll
        for (int nt = 0; nt < 4; nt++) {
            uint4 Bv = __ldg(cwB + tap * 512 + nt * 32);
            #pragma unroll
            for (int mt = 0; mt < 2; mt++) {
                mma_bf(acc[mt][nt], ah[mt][0], ah[mt][1], ah[mt][2], ah[mt][3], Bv.x, Bv.y);
                mma_bf(acc[mt][nt], ah[mt][0], ah[mt][1], ah[mt][2], ah[mt][3], Bv.z, Bv.w);
                mma_bf(acc[mt][nt], al[mt][0], al[mt][1], al[mt][2], al[mt][3], Bv.x, Bv.y);
            }
        }
    }
    // h = relu(conv), split, store to hS
    #pragma unroll
    for (int mt = 0; mt < 2; mt++) {
        int r = 32 * wm + 16 * mt + rt;
        #pragma unroll
        for (int nt = 0; nt < 4; nt++) {
            int kp = 16 * wn + 4 * nt + qt;
            float c0 = fmaxf(acc[mt][nt][0], 0.f), c1 = fmaxf(acc[mt][nt][1], 0.f);
            float c2 = fmaxf(acc[mt][nt][2], 0.f), c3 = fmaxf(acc[mt][nt][3], 0.f);
            u32 hi01, lo01, hi23, lo23;
            splitpk(c0, c1, hi01, lo01);
            splitpk(c2, c3, hi23, lo23);
            *(uint2*)(hS + (r * 68 + kp) * 2)       = make_uint2(hi01, lo01);
            *(uint2*)(hS + ((r + 8) * 68 + kp) * 2) = make_uint2(hi23, lo23);
        }
    }
    __syncthreads();   // hS complete; haloS dead (partials may overlay)

    // ================= d1 (k=128, n in 2 halves) fused with d2 =================
    float acc2[2][2][4];
    #pragma unroll
    for (int mt = 0; mt < 2; mt++)
        #pragma unroll
        for (int nt = 0; nt < 2; nt++)
            #pragma unroll
            for (int e = 0; e < 4; e++) acc2[mt][nt][e] = 0.f;

    #pragma unroll 1
    for (int hf = 0; hf < 2; hf++) {
        float acc1[2][4][4];
        #pragma unroll
        for (int nt = 0; nt < 4; nt++) {
            int n0 = 128 * hf + 32 * wn + 8 * nt + 2 * qt;
            float bb0 = __ldg(b1 + n0), bb1 = __ldg(b1 + n0 + 1);
            #pragma unroll
            for (int mt = 0; mt < 2; mt++) {
                acc1[mt][nt][0] = bb0; acc1[mt][nt][1] = bb1;
                acc1[mt][nt][2] = bb0; acc1[mt][nt][3] = bb1;
            }
        }
        #pragma unroll
        for (int kt = 0; kt < 8; kt++) {
            u32 ah[2][4], al[2][4];
            #pragma unroll
            for (int mt = 0; mt < 2; mt++) {
                const u32* hp = hA + mt * 2176 + kt * 16;
                uint2 A0 = *(const uint2*)hp;
                uint2 A1 = *(const uint2*)(hp + 1088);
                uint2 A2 = *(const uint2*)(hp + 8);
                uint2 A3 = *(const uint2*)(hp + 1096);
                ah[mt][0] = A0.x; al[mt][0] = A0.y;
                ah[mt][1] = A1.x; al[mt][1] = A1.y;
                ah[mt][2] = A2.x; al[mt][2] = A2.y;
                ah[mt][3] = A3.x; al[mt][3] = A3.y;
            }
            #pragma unroll
            for (int nt = 0; nt < 4; nt++) {
                uint4 Bv = __ldg(w1B + hf * 4096 + kt * 512 + nt * 32);
                #pragma unroll
                for (int mt = 0; mt < 2; mt++) {
                    mma_bf(acc1[mt][nt], ah[mt][0], ah[mt][1], ah[mt][2], ah[mt][3], Bv.x, Bv.y);
                    mma_bf(acc1[mt][nt], ah[mt][0], ah[mt][1], ah[mt][2], ah[mt][3], Bv.z, Bv.w);
                    mma_bf(acc1[mt][nt], al[mt][0], al[mt][1], al[mt][2], al[mt][3], Bv.x, Bv.y);
                }
            }
        }
        // a = relu(acc1) -> register A-frags -> d2 partial MMAs
        #pragma unroll
        for (int mt = 0; mt < 2; mt++) {
            #pragma unroll
            for (int ktl = 0; ktl < 2; ktl++) {
                float* cA = acc1[mt][2 * ktl];
                float* cB = acc1[mt][2 * ktl + 1];
                u32 ah0, al0, ah1, al1, ah2, al2, ah3, al3;
                splitpk(fmaxf(cA[0], 0.f), fmaxf(cA[1], 0.f), ah0, al0);
                splitpk(fmaxf(cA[2], 0.f), fmaxf(cA[3], 0.f), ah1, al1);
                splitpk(fmaxf(cB[0], 0.f), fmaxf(cB[1], 0.f), ah2, al2);
                splitpk(fmaxf(cB[2], 0.f), fmaxf(cB[3], 0.f), ah3, al3);
                #pragma unroll
                for (int nt2 = 0; nt2 < 2; nt2++) {
                    uint4 Bv = __ldg(w2B + nt2 * 512 + hf * 32 + ktl * 4);
                    mma_bf(acc2[mt][nt2], ah0, ah1, ah2, ah3, Bv.x, Bv.y);
                    mma_bf(acc2[mt][nt2], ah0, ah1, ah2, ah3, Bv.z, Bv.w);
                    mma_bf(acc2[mt][nt2], al0, al1, al2, al3, Bv.x, Bv.y);
                }
            }
        }
    }

    // ---- write d2 partials: part[wn][64][16] (overlays haloS) ----
    #pragma unroll
    for (int mt = 0; mt < 2; mt++) {
        int r = 32 * wm + 16 * mt + rt;
        #pragma unroll
        for (int nt2 = 0; nt2 < 2; nt2++) {
            int n0 = 8 * nt2 + 2 * qt;
            *(float2*)&part[(wn * 64 + r) * 16 + n0] =
                make_float2(acc2[mt][nt2][0], acc2[mt][nt2][1]);
            *(float2*)&part[(wn * 64 + r + 8) * 16 + n0] =
                make_float2(acc2[mt][nt2][2], acc2[mt][nt2][3]);
        }
    }
    __syncthreads();

    // ---- reduce 4 wn partials + masked residual update ----
    {
        int px = tid >> 2;
        int ch0 = (tid & 3) * 4;
        int P = (bI * Hdim + h0) * Wdim + px;
        const float* po = gsrc + (size_t)P * 16;
        float4 o = *(const float4*)(po + ch0);
        bool alive = po[0] > 0.1f;
        float4 d = make_float4(0.f, 0.f, 0.f, 0.f);
        #pragma unroll
        for (int g = 0; g < 4; g++) {
            float4 pv = *(const float4*)&part[(g * 64 + px) * 16 + ch0];
            d.x += pv.x; d.y += pv.y; d.z += pv.z; d.w += pv.w;
        }
        float out[4] = {o.x, o.y, o.z, o.w};
        #pragma unroll
        for (int c = 0; c < 4; c++) {
            int ch = ch0 + c;
            if (ch != 0 && alive) out[c] += (&d.x)[c] + __ldg(b2 + ch);
        }
        *(float4*)(gdst + (size_t)P * 16 + ch0) =
            make_float4(out[0], out[1], out[2], out[3]);
    }
}

__global__ void nca_softmax(float* __restrict__ out) {
    int pix = blockIdx.x * blockDim.x + threadIdx.x;
    if (pix >= NPIX) return;
    const float* g = g_bufs[0] + (size_t)pix * 16;
    float v[10];
    #pragma unroll
    for (int c = 0; c < 10; c++) v[c] = g[1 + c];
    float mx = v[0];
    #pragma unroll
    for (int c = 1; c < 10; c++) mx = fmaxf(mx, v[c]);
    float s = 0.0f;
    #pragma unroll
    for (int c = 0; c < 10; c++) { v[c] = __expf(v[c] - mx); s += v[c]; }
    float inv = 1.0f / s;
    float* o = out + (size_t)pix * 10;
    #pragma unroll
    for (int c = 0; c < 10; c++) o[c] = v[c] * inv;
}

extern "C" void kernel_launch(void* const* d_in, const int* in_sizes, int n_in,
                              void* d_out, int out_size) {
    const float* input = (const float*)d_in[0];
    const float* cw    = (const float*)d_in[1];
    const float* cb    = (const float*)d_in[2];
    const float* w1    = (const float*)d_in[3];
    const float* b1    = (const float*)d_in[4];
    const float* w2    = (const float*)d_in[5];
    const float* b2    = (const float*)d_in[6];

    cudaFuncSetAttribute(nca_step_h, cudaFuncAttributeMaxDynamicSharedMemorySize, SMEM_BYTES);

    nca_prep<<<54, 256>>>(cw, w1, w2);
    nca_init<<<NPIX / 256, 256>>>(input);
    for (int t = 0; t < TSTEPS; t++) {
        nca_step_h<<<Bdim * Hdim, 256, SMEM_BYTES>>>(t & 1, cb, b1, b2);
    }
    nca_softmax<<<NPIX / 256, 256>>>((float*)d_out);
}